// round 3
// baseline (speedup 1.0000x reference)
#include <cuda_runtime.h>
#include <cuda_bf16.h>

#define BB    8192
#define BLK   256
#define NSM   148
#define OCC   4
#define GRID  (NSM * OCC)   // 592 blocks, 4/SM guaranteed co-resident
#define K     64            // time-value buckets
#define CAP   256           // slots per bucket (~128 expected, 11+ sigma margin)
#define ECAP  256           // event slots per bucket (~64 expected)
#define IR    2             // i per thread
#define IBLK  (BLK * IR)    // 512 i per i-chunk
#define JC    64            // j per smem chunk
#define NJC   (BB / JC)     // 128 j-chunks

__device__ float2   g_jb[K * CAP];    // bucketed all rows {t, r}
__device__ float2   g_eb[K * ECAP];   // bucketed event rows {t, 1+r}
__device__ int      g_jcnt[K], g_ecnt[K];
__device__ int      g_jbase[K + 1], g_ebase[K + 1];
__device__ float2   g_jc[BB], g_ec[BB];   // compacted, bucket-sorted
__device__ int      g_nev;
__device__ unsigned g_bar1, g_bar2, g_bar3, g_done;
__device__ float    g_ps[GRID], g_pc[GRID];

__device__ __forceinline__ int bkt(float t) {
    int b = (int)(t * (float)K);
    return min(max(b, 0), K - 1);
}

__device__ __forceinline__ void gbar(unsigned* ctr, int tid) {
    __syncthreads();
    if (tid == 0) {
        __threadfence();
        atomicAdd(ctr, 1u);
        while (*(volatile unsigned*)ctr < (unsigned)GRID) { }
        __threadfence();
    }
    __syncthreads();
}

__global__ void __launch_bounds__(BLK, OCC) k_all(const float* __restrict__ risk,
                                                  const float* __restrict__ tm,
                                                  const int*   __restrict__ ev,
                                                  float*       __restrict__ out) {
    const int tid  = threadIdx.x;
    const int gtid = blockIdx.x * BLK + tid;

    // ---- Phase A: bucket-scatter all rows + event rows (blocks 0..31) ----
    if (gtid < BB) {
        float t = tm[gtid];
        float r = risk[gtid];
        int   b = bkt(t);
        int   p = atomicAdd(&g_jcnt[b], 1);
        g_jb[b * CAP + p] = make_float2(t, r);
        if (ev[gtid] == 1) {
            int q = atomicAdd(&g_ecnt[b], 1);
            g_eb[b * ECAP + q] = make_float2(t, 1.0f + r);
        }
    }
    gbar(&g_bar1, tid);

    // ---- Phase B: exclusive prefix sums (block 0, serial: 64 entries) ----
    if (blockIdx.x == 0 && tid == 0) {
        int ja = 0, ea = 0;
        for (int b = 0; b < K; b++) {
            g_jbase[b] = ja; ja += g_jcnt[b];
            g_ebase[b] = ea; ea += g_ecnt[b];
        }
        g_jbase[K] = ja; g_ebase[K] = ea;
        g_nev = ea;
    }
    gbar(&g_bar2, tid);

    // ---- Phase C: compact buckets into contiguous bucket-sorted arrays ----
    if (blockIdx.x < K) {
        int b  = blockIdx.x;
        int j0 = g_jbase[b], jn = g_jcnt[b];
        for (int p = tid; p < jn; p += BLK) g_jc[j0 + p] = g_jb[b * CAP + p];
        int e0 = g_ebase[b], en = g_ecnt[b];
        for (int p = tid; p < en; p += BLK) g_ec[e0 + p] = g_eb[b * ECAP + p];
    }
    gbar(&g_bar3, tid);

    // ---- Phase D: tiled pair loop with bucket-based classification ----
    const int nev = g_nev;
    __shared__ float2 sj[JC];
    __shared__ int    sjb[JC];

    float ls0 = 0.f, ls1 = 0.f;   // split accumulators (break FADD chain)
    float lc  = 0.f;

    const int nib    = (nev + IBLK - 1) / IBLK;
    const int ntiles = nib * NJC;

    for (int tl = blockIdx.x; tl < ntiles; tl += GRID) {
        int ib = tl % nib;
        int jb = tl / nib;
        int i0 = ib * IBLK;
        int iend = min(i0 + IBLK, nev);

        __syncthreads();
        if (tid < JC) {
            float2 p = g_jc[jb * JC + tid];
            sj[tid]  = p;
            sjb[tid] = bkt(p.x);
        }
        __syncthreads();

        int jb_lo = sjb[0];
        int jb_hi = sjb[JC - 1];
        int ib_lo = bkt(g_ec[i0].x);
        int ib_hi = bkt(g_ec[iend - 1].x);

        if (ib_lo > jb_hi) continue;   // every pair invalid (t_i > t_j)

        // load IR i's into registers
        float ti0, ci0, ti1, ci1;
        int   bi0, bi1;
        {
            int i = i0 + tid;
            if (i < iend) { float2 e = g_ec[i]; ti0 = e.x; ci0 = e.y; bi0 = bkt(e.x); }
            else { ti0 = __int_as_float(0x7f800000); ci0 = __int_as_float(0xff800000); bi0 = 1 << 30; }
            i = i0 + BLK + tid;
            if (i < iend) { float2 e = g_ec[i]; ti1 = e.x; ci1 = e.y; bi1 = bkt(e.x); }
            else { ti1 = __int_as_float(0x7f800000); ci1 = __int_as_float(0xff800000); bi1 = 1 << 30; }
        }

        if (ib_hi < jb_lo) {
            // FULL: every pair valid; count handled analytically. 3 instr/pair.
            #pragma unroll 8
            for (int j = 0; j < JC; j++) {
                float2 p = sj[j];
                ls0 += fmaxf(ci0 - p.y, 0.f);
                ls1 += fmaxf(ci1 - p.y, 0.f);
            }
        } else {
            // MIXED: valid <=> t_i < t_j (bucket ranges make this exact).
            // Count only same-bucket valid pairs (cross-bucket counted analytically).
            #pragma unroll 4
            for (int j = 0; j < JC; j++) {
                float2 p  = sj[j];
                int    bj = sjb[j];
                bool v0 = ti0 < p.x;
                bool v1 = ti1 < p.x;
                float h0 = fmaxf(ci0 - p.y, 0.f);
                float h1 = fmaxf(ci1 - p.y, 0.f);
                if (v0) ls0 += h0;
                if (v1) ls1 += h1;
                if (v0 && bi0 == bj) lc += 1.f;
                if (v1 && bi1 == bj) lc += 1.f;
            }
        }
    }

    float lsum = ls0 + ls1;

    // ---- block reduce -> per-block partials ----
    #pragma unroll
    for (int o = 16; o; o >>= 1) {
        lsum += __shfl_down_sync(0xffffffffu, lsum, o);
        lc   += __shfl_down_sync(0xffffffffu, lc, o);
    }
    __shared__ float ws[BLK / 32], wc[BLK / 32];
    if ((tid & 31) == 0) { ws[tid >> 5] = lsum; wc[tid >> 5] = lc; }
    __syncthreads();
    if (tid == 0) {
        float s = 0.f, c = 0.f;
        #pragma unroll
        for (int k = 0; k < BLK / 32; k++) { s += ws[k]; c += wc[k]; }
        g_ps[blockIdx.x] = s;
        g_pc[blockIdx.x] = c;
    }

    // ---- finish: last block reduces + analytic cross-bucket count ----
    __shared__ int amLast;
    if (tid == 0) {
        __threadfence();
        amLast = (atomicAdd(&g_done, 1u) == GRID - 1);
    }
    __syncthreads();

    if (amLast) {
        __threadfence();
        double s = 0.0, c = 0.0;
        for (int i = tid; i < GRID; i += BLK) {
            s += (double)g_ps[i];
            c += (double)g_pc[i];
        }
        for (int b = tid; b < K; b += BLK)
            c += (double)g_jcnt[b] * (double)g_ebase[b];

        #pragma unroll
        for (int o = 16; o; o >>= 1) {
            s += __shfl_down_sync(0xffffffffu, s, o);
            c += __shfl_down_sync(0xffffffffu, c, o);
        }
        __shared__ double fs[BLK / 32], fc[BLK / 32];
        if ((tid & 31) == 0) { fs[tid >> 5] = s; fc[tid >> 5] = c; }
        __syncthreads();
        if (tid == 0) {
            double S = 0.0, C = 0.0;
            #pragma unroll
            for (int k = 0; k < BLK / 32; k++) { S += fs[k]; C += fc[k]; }
            out[0] = (C == 0.0) ? 0.f : (float)(S / C);
        }
        __syncthreads();
        // reset device state for next graph replay
        for (int b = tid; b < K; b += BLK) { g_jcnt[b] = 0; g_ecnt[b] = 0; }
        if (tid == 0) {
            g_bar1 = 0; g_bar2 = 0; g_bar3 = 0; g_done = 0; g_nev = 0;
        }
    }
}

extern "C" void kernel_launch(void* const* d_in, const int* in_sizes, int n_in,
                              void* d_out, int out_size) {
    // metadata order: z (unused), risk, time, event
    const float* risk = (const float*)d_in[1];
    const float* tm   = (const float*)d_in[2];
    const int*   ev   = (const int*)d_in[3];
    float*       out  = (float*)d_out;

    k_all<<<GRID, BLK>>>(risk, tm, ev, out);
}

// round 4
// speedup vs baseline: 1.1133x; 1.1133x over previous
#include <cuda_runtime.h>
#include <cuda_bf16.h>

#define BB    8192
#define BLK   512
#define NSM   148
#define OCC   4
#define GRID  (NSM * OCC)   // 592 blocks, 4/SM co-resident (needed for grid barrier)
#define IR    2
#define IBLK  (BLK * IR)    // 1024 i per i-chunk
#define JMAX  128           // max j-segment length (worst case nev=8192 -> 111)

__device__ float2   g_ec[BB];    // compacted event rows {time_i, 1+risk_i}
__device__ int      g_nev;
__device__ unsigned g_bar, g_done;
__device__ float    g_ps[GRID];
__device__ int      g_pc[GRID];

__global__ void __launch_bounds__(BLK, OCC) k_all(const float* __restrict__ risk,
                                                  const float* __restrict__ tm,
                                                  const int*   __restrict__ ev,
                                                  float*       __restrict__ out) {
    const int tid = threadIdx.x;
    const int bid = blockIdx.x;
    const int gtid = bid * BLK + tid;

    // ---- Phase A: warp-aggregated event compaction (first 16 blocks) ----
    if (gtid < BB) {
        float t = tm[gtid];
        float r = risk[gtid];
        int   e = ev[gtid];
        unsigned m = __ballot_sync(0xffffffffu, e == 1);
        int base = 0;
        if ((tid & 31) == 0 && m) base = atomicAdd(&g_nev, __popc(m));
        base = __shfl_sync(0xffffffffu, base, 0);
        if (e == 1) {
            int p = base + __popc(m & ((1u << (tid & 31)) - 1u));
            g_ec[p] = make_float2(t, 1.0f + r);
        }
    }

    // ---- single software grid barrier ----
    __syncthreads();
    if (tid == 0) {
        __threadfence();
        atomicAdd(&g_bar, 1u);
        while (*(volatile unsigned*)&g_bar < (unsigned)GRID) { }
        __threadfence();
    }
    __syncthreads();

    const int nev = *(volatile int*)&g_nev;
    const int nib = (nev + IBLK - 1) / IBLK;          // i-chunks (~4)

    float ls0 = 0.f, ls1 = 0.f;
    int   lc0 = 0,   lc1 = 0;

    __shared__ float2 sj[JMAX];

    if (nib > 0) {
        const int NJS  = GRID / nib;                  // j-segments (~148)
        const int jseg = (BB + NJS - 1) / NJS;        // ~56 (<= 111 worst case)

        if (bid < nib * NJS) {
            const int ic = bid % nib;
            const int js = bid / nib;
            const int j0 = js * jseg;
            const int j1 = min(j0 + jseg, BB);
            const int jn = j1 - j0;

            // stage this block's j-segment ONCE
            for (int j = tid; j < jn; j += BLK)
                sj[j] = make_float2(tm[j0 + j], risk[j0 + j]);
            __syncthreads();

            // i-values live in registers for the whole kernel
            float ti0, ci0, ti1, ci1;
            {
                int i = ic * IBLK + tid;
                if (i < nev) { float2 e = g_ec[i]; ti0 = e.x; ci0 = e.y; }
                else         { ti0 = __int_as_float(0x7f800000); ci0 = 0.f; }
                i += BLK;
                if (i < nev) { float2 e = g_ec[i]; ti1 = e.x; ci1 = e.y; }
                else         { ti1 = __int_as_float(0x7f800000); ci1 = 0.f; }
            }

            #pragma unroll 4
            for (int j = 0; j < jn; j++) {
                float2 p = sj[j];                     // LDS.64 broadcast
                bool  v0 = ti0 < p.x;
                bool  v1 = ti1 < p.x;
                float h0 = fmaxf(ci0 - p.y, 0.f);
                float h1 = fmaxf(ci1 - p.y, 0.f);
                if (v0) { ls0 += h0; lc0 += 1; }      // count on alu pipe (IADD)
                if (v1) { ls1 += h1; lc1 += 1; }
            }
        }
    }

    float lsum = ls0 + ls1;
    int   lcnt = lc0 + lc1;

    // ---- block reduce -> per-block partial ----
    #pragma unroll
    for (int o = 16; o; o >>= 1) {
        lsum += __shfl_down_sync(0xffffffffu, lsum, o);
        lcnt += __shfl_down_sync(0xffffffffu, lcnt, o);
    }
    __shared__ float ws[BLK / 32];
    __shared__ int   wc[BLK / 32];
    if ((tid & 31) == 0) { ws[tid >> 5] = lsum; wc[tid >> 5] = lcnt; }
    __syncthreads();
    if (tid == 0) {
        float s = 0.f; int c = 0;
        #pragma unroll
        for (int k = 0; k < BLK / 32; k++) { s += ws[k]; c += wc[k]; }
        g_ps[bid] = s;
        g_pc[bid] = c;
    }

    // ---- last block: final reduce (double) + output + state reset ----
    __shared__ int amLast;
    if (tid == 0) {
        __threadfence();
        amLast = (atomicAdd(&g_done, 1u) == GRID - 1);
    }
    __syncthreads();

    if (amLast) {
        __threadfence();
        double s = 0.0, c = 0.0;
        for (int i = tid; i < GRID; i += BLK) {
            s += (double)g_ps[i];
            c += (double)g_pc[i];
        }
        #pragma unroll
        for (int o = 16; o; o >>= 1) {
            s += __shfl_down_sync(0xffffffffu, s, o);
            c += __shfl_down_sync(0xffffffffu, c, o);
        }
        __shared__ double fs[BLK / 32], fc[BLK / 32];
        if ((tid & 31) == 0) { fs[tid >> 5] = s; fc[tid >> 5] = c; }
        __syncthreads();
        if (tid == 0) {
            double S = 0.0, C = 0.0;
            #pragma unroll
            for (int k = 0; k < BLK / 32; k++) { S += fs[k]; C += fc[k]; }
            out[0] = (C == 0.0) ? 0.f : (float)(S / C);
            g_bar  = 0;     // reset for next graph replay
            g_done = 0;
            g_nev  = 0;
        }
    }
}

extern "C" void kernel_launch(void* const* d_in, const int* in_sizes, int n_in,
                              void* d_out, int out_size) {
    // metadata order: z (unused), risk, time, event
    const float* risk = (const float*)d_in[1];
    const float* tm   = (const float*)d_in[2];
    const int*   ev   = (const int*)d_in[3];
    float*       out  = (float*)d_out;

    k_all<<<GRID, BLK>>>(risk, tm, ev, out);
}